// round 1
// baseline (speedup 1.0000x reference)
#include <cuda_runtime.h>
#include <cstdint>

#define NPTS   8192
#define DIM    256
#define NBANDS 16
#define NROWS  8

// scratch (allocation-free rule: device globals)
__device__ int   g_keys[NBANDS * NPTS];   // keys[b*NPTS + n]
__device__ float g_invn[NPTS];

// ---------------------------------------------------------------------------
// Kernel A: LSH band keys.  block = 256 threads handles 32 points.
//   thread -> (band b = tid&15, group ng = tid>>4), each thread does 2 points.
// ---------------------------------------------------------------------------
__global__ void __launch_bounds__(256) keys_kernel(const float* __restrict__ Z,
                                                   const float* __restrict__ planes) {
    __shared__ __align__(16) float Zs[32][DIM];   // 32 KB
    const int tid   = threadIdx.x;
    const int nbase = blockIdx.x * 32;

    // stage 32 Z rows (32*256 floats = 2048 float4)
    const float4* Zv  = (const float4*)(Z + (size_t)nbase * DIM);
    float4*       Zsv = (float4*)&Zs[0][0];
    #pragma unroll
    for (int i = tid; i < 32 * (DIM / 4); i += 256) Zsv[i] = Zv[i];
    __syncthreads();

    const int b  = tid & 15;
    const int ng = tid >> 4;            // 0..15
    const int n0 = ng * 2;

    int key0 = 0, key1 = 0;
    for (int r = 0; r < NROWS; r++) {
        const float4* pl = (const float4*)(planes + (size_t)(b * NROWS + r) * DIM);
        float acc0 = 0.f, acc1 = 0.f;
        #pragma unroll
        for (int d4 = 0; d4 < DIM / 4; d4++) {
            float4 p  = pl[d4];
            float4 z0 = *(const float4*)&Zs[n0 + 0][d4 << 2];
            float4 z1 = *(const float4*)&Zs[n0 + 1][d4 << 2];
            acc0 += p.x * z0.x + p.y * z0.y + p.z * z0.z + p.w * z0.w;
            acc1 += p.x * z1.x + p.y * z1.y + p.z * z1.z + p.w * z1.w;
        }
        if (acc0 >= 0.f) key0 |= (1 << r);
        if (acc1 >= 0.f) key1 |= (1 << r);
    }
    g_keys[b * NPTS + nbase + n0 + 0] = key0;
    g_keys[b * NPTS + nbase + n0 + 1] = key1;
}

// ---------------------------------------------------------------------------
// Kernel B: inverse row norms.  one warp per row.
// ---------------------------------------------------------------------------
__global__ void __launch_bounds__(256) norm_kernel(const float* __restrict__ Z) {
    const int row  = blockIdx.x * 8 + (threadIdx.x >> 5);
    const int lane = threadIdx.x & 31;
    const float4* zr = (const float4*)(Z + (size_t)row * DIM);
    float4 a = zr[lane];
    float4 c = zr[lane + 32];
    float s = a.x * a.x + a.y * a.y + a.z * a.z + a.w * a.w
            + c.x * c.x + c.y * c.y + c.z * c.z + c.w * c.w;
    #pragma unroll
    for (int o = 16; o; o >>= 1) s += __shfl_xor_sync(0xFFFFFFFFu, s, o);
    if (lane == 0) g_invn[row] = rsqrtf(s);
}

// ---------------------------------------------------------------------------
// Kernel C: sim GEMM (upper-triangular tiles) + fused LSH epilogue + mirror.
//   BM=BN=128, BK=16, 256 threads, 8x8 microtile per thread.
// ---------------------------------------------------------------------------
#define BM 128
#define BN 128
#define BK 16
__global__ void __launch_bounds__(256, 2) sim_kernel(const float* __restrict__ Z,
                                                     float* __restrict__ out) {
    const int tj = blockIdx.x;   // column tile
    const int ti = blockIdx.y;   // row tile
    if (ti > tj) return;         // compute upper triangle only

    __shared__ __align__(16) float As[BK][BM];
    __shared__ __align__(16) float Bs[BK][BN];
    __shared__ __align__(16) float Ts[32][132];   // transpose staging (padded)

    const int tid = threadIdx.x;
    const int tx  = tid & 15;    // 16 col-groups
    const int ty  = tid >> 4;    // 16 row-groups

    float c[8][8];
    #pragma unroll
    for (int i = 0; i < 8; i++)
        #pragma unroll
        for (int j = 0; j < 8; j++) c[i][j] = 0.f;

    const float* Abase = Z + (size_t)(ti * BM) * DIM;
    const float* Bbase = Z + (size_t)(tj * BN) * DIM;

    for (int k0 = 0; k0 < DIM; k0 += BK) {
        // load 128x16 A and B tiles (transposed into smem)
        #pragma unroll
        for (int l = 0; l < 2; l++) {
            int f   = tid + l * 256;       // 0..511
            int row = f >> 2;              // 0..127
            int q   = f & 3;               // float4 quad within BK
            float4 a = *(const float4*)(Abase + (size_t)row * DIM + k0 + q * 4);
            As[q * 4 + 0][row] = a.x; As[q * 4 + 1][row] = a.y;
            As[q * 4 + 2][row] = a.z; As[q * 4 + 3][row] = a.w;
            float4 b = *(const float4*)(Bbase + (size_t)row * DIM + k0 + q * 4);
            Bs[q * 4 + 0][row] = b.x; Bs[q * 4 + 1][row] = b.y;
            Bs[q * 4 + 2][row] = b.z; Bs[q * 4 + 3][row] = b.w;
        }
        __syncthreads();

        #pragma unroll
        for (int kk = 0; kk < BK; kk++) {
            float a[8], b[8];
            *(float4*)&a[0] = *(const float4*)&As[kk][ty * 8];
            *(float4*)&a[4] = *(const float4*)&As[kk][ty * 8 + 4];
            *(float4*)&b[0] = *(const float4*)&Bs[kk][tx * 8];
            *(float4*)&b[4] = *(const float4*)&Bs[kk][tx * 8 + 4];
            #pragma unroll
            for (int i = 0; i < 8; i++)
                #pragma unroll
                for (int j = 0; j < 8; j++) c[i][j] += a[i] * b[j];
        }
        __syncthreads();
    }

    // ---- epilogue: sim = dot * invn_i * invn_j; threshold; lazy band count ----
    const int gi0 = ti * BM + ty * 8;
    const int gj0 = tj * BN + tx * 8;
    float ri[8], rj[8];
    #pragma unroll
    for (int i = 0; i < 8; i++) ri[i] = g_invn[gi0 + i];
    #pragma unroll
    for (int j = 0; j < 8; j++) rj[j] = g_invn[gj0 + j];

    #pragma unroll
    for (int i = 0; i < 8; i++) {
        #pragma unroll
        for (int j = 0; j < 8; j++) {
            float s = c[i][j] * ri[i] * rj[j];
            float v = 0.f;
            int gi = gi0 + i, gj = gj0 + j;
            if (s >= 0.5f && gi != gj) {   // ~never taken with Gaussian data
                int cnt = 0;
                #pragma unroll
                for (int bb = 0; bb < NBANDS; bb++)
                    cnt += (g_keys[bb * NPTS + gi] == g_keys[bb * NPTS + gj]) ? 1 : 0;
                v = (float)cnt * s;
            }
            c[i][j] = v;
        }
    }

    // ---- direct store (coalesced float4) ----
    #pragma unroll
    for (int i = 0; i < 8; i++) {
        size_t ob = (size_t)(gi0 + i) * NPTS + gj0;
        *(float4*)&out[ob]     = *(const float4*)&c[i][0];
        *(float4*)&out[ob + 4] = *(const float4*)&c[i][4];
    }

    // ---- mirror store via smem transpose (skip diagonal tiles) ----
    if (ti == tj) return;
    #pragma unroll
    for (int ch = 0; ch < 4; ch++) {       // 32-column strips
        __syncthreads();
        if ((tx >> 2) == ch) {
            int jb = (tx & 3) * 8;          // local col within strip
            #pragma unroll
            for (int i = 0; i < 8; i++)
                #pragma unroll
                for (int j = 0; j < 8; j++)
                    Ts[jb + j][ty * 8 + i] = c[i][j];
        }
        __syncthreads();
        int jr = tid >> 3;                  // 0..31: row within strip
        int c0 = (tid & 7) * 4;             // 0..28: col group
        size_t ob = (size_t)(tj * BN + ch * 32 + jr) * NPTS + ti * BM;
        #pragma unroll
        for (int u = 0; u < 4; u++)
            *(float4*)&out[ob + c0 + u * 32] = *(const float4*)&Ts[jr][c0 + u * 32];
    }
}

// ---------------------------------------------------------------------------
extern "C" void kernel_launch(void* const* d_in, const int* in_sizes, int n_in,
                              void* d_out, int out_size) {
    const float* Z      = (const float*)d_in[0];
    const float* planes = (const float*)d_in[1];
    float*       out    = (float*)d_out;

    keys_kernel<<<NPTS / 32, 256>>>(Z, planes);
    norm_kernel<<<NPTS / 8, 256>>>(Z);
    dim3 grid(NPTS / BN, NPTS / BM);
    sim_kernel<<<grid, 256>>>(Z, out);
}

// round 3
// speedup vs baseline: 4.5694x; 4.5694x over previous
#include <cuda_runtime.h>
#include <cuda_bf16.h>
#include <cstdint>

#define NPTS   8192
#define DIM    256
#define NBANDS 16
#define NROWS  8

// scratch (allocation-free rule: device globals)
__device__ int g_keys[NBANDS * NPTS];
__device__ __align__(16) __nv_bfloat16 g_znb[(size_t)NPTS * DIM];   // 4 MB, row-normalized bf16 Z

// ---------------------------------------------------------------------------
// helpers (compute_103-baseline PTX only: cp.async / ldmatrix / mma.sync)
// ---------------------------------------------------------------------------
__device__ __forceinline__ uint32_t smem_u32(const void* p) {
    uint32_t a;
    asm("{ .reg .u64 t; cvta.to.shared.u64 t, %1; cvt.u32.u64 %0, t; }" : "=r"(a) : "l"(p));
    return a;
}
__device__ __forceinline__ void cp_async16(uint32_t dst, const void* src) {
    asm volatile("cp.async.cg.shared.global [%0], [%1], 16;" :: "r"(dst), "l"(src) : "memory");
}
__device__ __forceinline__ void cp_commit() {
    asm volatile("cp.async.commit_group;" ::: "memory");
}
template <int N> __device__ __forceinline__ void cp_wait() {
    asm volatile("cp.async.wait_group %0;" :: "n"(N) : "memory");
}
__device__ __forceinline__ void ldsm4(uint32_t r[4], uint32_t addr) {
    asm volatile("ldmatrix.sync.aligned.m8n8.x4.shared.b16 {%0,%1,%2,%3}, [%4];"
                 : "=r"(r[0]), "=r"(r[1]), "=r"(r[2]), "=r"(r[3]) : "r"(addr));
}
__device__ __forceinline__ void mma16816(float c[4], const uint32_t a[4],
                                         uint32_t b0, uint32_t b1) {
    asm volatile(
        "mma.sync.aligned.m16n8k16.row.col.f32.bf16.bf16.f32 "
        "{%0,%1,%2,%3}, {%4,%5,%6,%7}, {%8,%9}, {%0,%1,%2,%3};"
        : "+f"(c[0]), "+f"(c[1]), "+f"(c[2]), "+f"(c[3])
        : "r"(a[0]), "r"(a[1]), "r"(a[2]), "r"(a[3]), "r"(b0), "r"(b1));
}

// ---------------------------------------------------------------------------
// Kernel 1: row norms + bf16 conversion (pre-normalized Z). warp per row.
// ---------------------------------------------------------------------------
__global__ void __launch_bounds__(256) normconv_kernel(const float* __restrict__ Z) {
    const int row  = blockIdx.x * 8 + (threadIdx.x >> 5);
    const int lane = threadIdx.x & 31;
    const float4* zr = (const float4*)(Z + (size_t)row * DIM);
    float4 a = zr[lane];
    float4 c = zr[lane + 32];
    float s = a.x * a.x + a.y * a.y + a.z * a.z + a.w * a.w
            + c.x * c.x + c.y * c.y + c.z * c.z + c.w * c.w;
    #pragma unroll
    for (int o = 16; o; o >>= 1) s += __shfl_xor_sync(0xFFFFFFFFu, s, o);
    float inv = rsqrtf(s);

    uint2* ob = (uint2*)(g_znb + (size_t)row * DIM);
    __nv_bfloat162 h0 = __float22bfloat162_rn(make_float2(a.x * inv, a.y * inv));
    __nv_bfloat162 h1 = __float22bfloat162_rn(make_float2(a.z * inv, a.w * inv));
    __nv_bfloat162 h2 = __float22bfloat162_rn(make_float2(c.x * inv, c.y * inv));
    __nv_bfloat162 h3 = __float22bfloat162_rn(make_float2(c.z * inv, c.w * inv));
    uint2 w0, w1;
    w0.x = *(uint32_t*)&h0; w0.y = *(uint32_t*)&h1;
    w1.x = *(uint32_t*)&h2; w1.y = *(uint32_t*)&h3;
    ob[lane]      = w0;
    ob[lane + 32] = w1;
}

// ---------------------------------------------------------------------------
// Kernel 2: LSH keys, GEMM-style. block = 64 points x all 128 planes.
// ---------------------------------------------------------------------------
__global__ void __launch_bounds__(256) keys_kernel(const float* __restrict__ Z,
                                                   const float* __restrict__ planes) {
    __shared__ float Ps[128][36];
    __shared__ float Zs[64][36];
    const int tid   = threadIdx.x;
    const int pg    = tid & 31;
    const int bb    = tid >> 5;
    const int nbase = blockIdx.x * 64;

    float acc[2][8][2];
    #pragma unroll
    for (int bi = 0; bi < 2; bi++)
        #pragma unroll
        for (int r = 0; r < 8; r++) acc[bi][r][0] = acc[bi][r][1] = 0.f;

    for (int kc = 0; kc < 8; kc++) {
        #pragma unroll
        for (int l = 0; l < 4; l++) {
            int f = tid + l * 256;
            int row = f >> 3, q = f & 7;
            *(float4*)&Ps[row][q * 4] =
                *(const float4*)(planes + (size_t)row * DIM + kc * 32 + q * 4);
        }
        #pragma unroll
        for (int l = 0; l < 2; l++) {
            int f = tid + l * 256;
            int row = f >> 3, q = f & 7;
            *(float4*)&Zs[row][q * 4] =
                *(const float4*)(Z + (size_t)(nbase + row) * DIM + kc * 32 + q * 4);
        }
        __syncthreads();

        #pragma unroll
        for (int q = 0; q < 8; q++) {
            float4 z0 = *(const float4*)&Zs[2 * pg + 0][q * 4];
            float4 z1 = *(const float4*)&Zs[2 * pg + 1][q * 4];
            #pragma unroll
            for (int bi = 0; bi < 2; bi++)
                #pragma unroll
                for (int r = 0; r < 8; r++) {
                    float4 p = *(const float4*)&Ps[(bb + bi * 8) * 8 + r][q * 4];
                    acc[bi][r][0] += p.x * z0.x + p.y * z0.y + p.z * z0.z + p.w * z0.w;
                    acc[bi][r][1] += p.x * z1.x + p.y * z1.y + p.z * z1.z + p.w * z1.w;
                }
        }
        __syncthreads();
    }

    #pragma unroll
    for (int bi = 0; bi < 2; bi++)
        #pragma unroll
        for (int pt = 0; pt < 2; pt++) {
            int key = 0;
            #pragma unroll
            for (int r = 0; r < 8; r++)
                if (acc[bi][r][pt] >= 0.f) key |= (1 << r);
            g_keys[(bb + bi * 8) * NPTS + nbase + 2 * pg + pt] = key;
        }
}

// ---------------------------------------------------------------------------
// Kernel 3: sim GEMM on HMMA (mma.sync bf16). 128x128 tile, triangular+mirror.
//   K chunks of 64 bf16 (128B rows, XOR-swizzled), cp.async double buffer.
//   8 warps as 4(m) x 2(n): warp tile 32 x 64.
// smem layout (dynamic, 67584 B):
//   pipeline: A0 [0,16K) B0 [16K,32K) A1 [32K,48K) B1 [48K,64K)
//   epilogue: f32 stage [128][132] overlays everything
// ---------------------------------------------------------------------------
#define STG_LD 132
extern __shared__ uint8_t s_dyn[];

__global__ void __launch_bounds__(256) simmma_kernel(float* __restrict__ out) {
    const int tj = blockIdx.x;
    const int ti = blockIdx.y;
    if (ti > tj) return;

    const int tid = threadIdx.x;
    const int wid = tid >> 5, lid = tid & 31;
    const int wm = wid >> 1, wn = wid & 1;           // warp tile: rows 32*wm, cols 64*wn
    const uint32_t sbase = smem_u32(s_dyn);

    const __nv_bfloat16* Arow = g_znb + (size_t)(ti * 128) * DIM;
    const __nv_bfloat16* Brow = g_znb + (size_t)(tj * 128) * DIM;

    // prefetch chunk c into buffer (c&1)
    auto prefetch = [&](int c) {
        uint32_t sA = sbase + (c & 1) * 32768;
        uint32_t sB = sA + 16384;
        #pragma unroll
        for (int l = 0; l < 4; l++) {
            int f   = tid + l * 256;               // 0..1023 16B-units
            int row = f >> 3, c16 = f & 7;
            uint32_t sw = (uint32_t)row * 128 + ((uint32_t)(c16 ^ (row & 7)) << 4);
            cp_async16(sA + sw, Arow + (size_t)row * DIM + c * 64 + c16 * 8);
            cp_async16(sB + sw, Brow + (size_t)row * DIM + c * 64 + c16 * 8);
        }
        cp_commit();
    };

    float c[2][8][4];
    #pragma unroll
    for (int mt = 0; mt < 2; mt++)
        #pragma unroll
        for (int nt = 0; nt < 8; nt++)
            #pragma unroll
            for (int u = 0; u < 4; u++) c[mt][nt][u] = 0.f;

    prefetch(0);

    const int lr = lid & 15;          // ldmatrix row within 16-row tile
    const int lc = lid >> 4;          // ldmatrix 16B col-group (0/1)

    for (int ch = 0; ch < 4; ch++) {
        if (ch + 1 < 4) { prefetch(ch + 1); cp_wait<1>(); }
        else            { cp_wait<0>(); }
        __syncthreads();

        uint32_t sA = sbase + (ch & 1) * 32768;
        uint32_t sB = sA + 16384;

        #pragma unroll
        for (int ks = 0; ks < 4; ks++) {
            uint32_t a[2][4], b[4][4];
            #pragma unroll
            for (int mt = 0; mt < 2; mt++) {
                int rg = wm * 32 + mt * 16 + lr;
                int cg = ks * 2 + lc;
                ldsm4(a[mt], sA + (uint32_t)rg * 128 + ((uint32_t)(cg ^ (rg & 7)) << 4));
            }
            #pragma unroll
            for (int ng = 0; ng < 4; ng++) {
                int rg = wn * 64 + ng * 16 + lr;
                int cg = ks * 2 + lc;
                ldsm4(b[ng], sB + (uint32_t)rg * 128 + ((uint32_t)(cg ^ (rg & 7)) << 4));
            }
            #pragma unroll
            for (int mt = 0; mt < 2; mt++)
                #pragma unroll
                for (int ng = 0; ng < 4; ng++) {
                    mma16816(c[mt][2 * ng + 0], a[mt], b[ng][0], b[ng][2]);
                    mma16816(c[mt][2 * ng + 1], a[mt], b[ng][1], b[ng][3]);
                }
        }
        __syncthreads();   // buffer consumed; safe for next prefetch overwrite
    }

    // ---- thresholded epilogue (values in fragments) ----
    const int gi0 = ti * 128, gj0 = tj * 128;
    const int fr = lid >> 2;          // fragment row within m16 tile (0..7)
    const int fc = (lid & 3) * 2;     // fragment col pair base (0..6)
    #pragma unroll
    for (int mt = 0; mt < 2; mt++)
        #pragma unroll
        for (int nt = 0; nt < 8; nt++)
            #pragma unroll
            for (int u = 0; u < 4; u++) {
                float v = c[mt][nt][u];
                int i = wm * 32 + mt * 16 + fr + (u >> 1) * 8;
                int j = wn * 64 + nt * 8 + fc + (u & 1);
                int gi = gi0 + i, gj = gj0 + j;
                float o = 0.f;
                if (v >= 0.5f && gi != gj) {       // ~never taken (8-sigma margin)
                    int cnt = 0;
                    #pragma unroll
                    for (int b2 = 0; b2 < NBANDS; b2++)
                        cnt += (g_keys[b2 * NPTS + gi] == g_keys[b2 * NPTS + gj]) ? 1 : 0;
                    o = (float)cnt * v;
                }
                c[mt][nt][u] = o;
            }

    // ---- pass 1: stage [i][j], direct store ----
    float* stg = (float*)s_dyn;
    #pragma unroll
    for (int mt = 0; mt < 2; mt++)
        #pragma unroll
        for (int nt = 0; nt < 8; nt++) {
            int i0 = wm * 32 + mt * 16 + fr;
            int j  = wn * 64 + nt * 8 + fc;
            *(float2*)&stg[(i0    ) * STG_LD + j] = make_float2(c[mt][nt][0], c[mt][nt][1]);
            *(float2*)&stg[(i0 + 8) * STG_LD + j] = make_float2(c[mt][nt][2], c[mt][nt][3]);
        }
    __syncthreads();
    #pragma unroll
    for (int l = 0; l < 16; l++) {
        int f = tid + l * 256;
        int i = f >> 5, q = f & 31;
        *(float4*)(out + (size_t)(gi0 + i) * NPTS + gj0 + q * 4) =
            *(const float4*)&stg[i * STG_LD + q * 4];
    }

    // ---- pass 2: stage transposed [j][i], mirror store ----
    if (ti == tj) return;
    __syncthreads();
    #pragma unroll
    for (int mt = 0; mt < 2; mt++)
        #pragma unroll
        for (int nt = 0; nt < 8; nt++) {
            int i0 = wm * 32 + mt * 16 + fr;
            int j  = wn * 64 + nt * 8 + fc;
            stg[(j    ) * STG_LD + i0    ] = c[mt][nt][0];
            stg[(j + 1) * STG_LD + i0    ] = c[mt][nt][1];
            stg[(j    ) * STG_LD + i0 + 8] = c[mt][nt][2];
            stg[(j + 1) * STG_LD + i0 + 8] = c[mt][nt][3];
        }
    __syncthreads();
    #pragma unroll
    for (int l = 0; l < 16; l++) {
        int f = tid + l * 256;
        int j = f >> 5, q = f & 31;
        *(float4*)(out + (size_t)(gj0 + j) * NPTS + gi0 + q * 4) =
            *(const float4*)&stg[j * STG_LD + q * 4];
    }
}

// ---------------------------------------------------------------------------
extern "C" void kernel_launch(void* const* d_in, const int* in_sizes, int n_in,
                              void* d_out, int out_size) {
    const float* Z      = (const float*)d_in[0];
    const float* planes = (const float*)d_in[1];
    float*       out    = (float*)d_out;

    static const int SMEM_BYTES = 128 * STG_LD * 4;   // 67584 >= 64K pipeline
    cudaFuncSetAttribute(simmma_kernel, cudaFuncAttributeMaxDynamicSharedMemorySize,
                         SMEM_BYTES);

    normconv_kernel<<<NPTS / 8, 256>>>(Z);
    keys_kernel<<<NPTS / 64, 256>>>(Z, planes);
    dim3 grid(NPTS / 128, NPTS / 128);
    simmma_kernel<<<grid, 256, SMEM_BYTES>>>(out);
}